// round 4
// baseline (speedup 1.0000x reference)
#include <cuda_runtime.h>

#define NN 200000
#define NNZC 3200000
#define NG 256
#define SCAN_BS 1024
#define NBLK_SCAN ((NN + SCAN_BS - 1) / SCAN_BS)   // 196

// ---------------- device scratch (no allocations allowed) ----------------
__device__ __align__(16) int   g_ptr_up[NN + 1];
__device__ __align__(16) int   g_ptr_dn[NN + 1];
__device__ __align__(16) int   g_cnt_up[NN];       // counts, then cursor
__device__ __align__(16) int   g_cnt_dn[NN];
__device__ __align__(16) int   g_col_up[NNZC];
__device__ __align__(16) int   g_col_dn[NNZC];
__device__ __align__(16) float g_cval_up[NNZC];
__device__ __align__(16) float g_cval_dn[NNZC];
__device__ __align__(16) int   g_bsum[NBLK_SCAN];
__device__ __align__(16) float g_H[(size_t)NN * 64];
__device__ __align__(16) float g_X[(size_t)NN * 32];
__device__ __align__(16) float g_Y[(size_t)NN * 64];
__device__ __align__(16) float g_S2a[NN];
__device__ __align__(16) float g_S2b[NN];
__device__ __align__(16) float g_psum[NG * 64];
__device__ __align__(16) float g_pcnt[NG];

// ---------------- zero scratch that needs it ----------------
__global__ void zero_kernel() {
    int i = blockIdx.x * blockDim.x + threadIdx.x;
    if (i < NN) { g_cnt_up[i] = 0; g_cnt_dn[i] = 0; }
    if (i < NG * 64) g_psum[i] = 0.f;
    if (i < NG) g_pcnt[i] = 0.f;
}

// ---------------- CSR build ----------------
__global__ void count_kernel(const int* __restrict__ rows, int which) {
    int e = blockIdx.x * blockDim.x + threadIdx.x;
    if (e >= NNZC) return;
    int r = rows[e];
    atomicAdd(which ? &g_cnt_dn[r] : &g_cnt_up[r], 1);
}

__global__ __launch_bounds__(SCAN_BS) void scan1_kernel(int which) {
    __shared__ int s[SCAN_BS];
    const int* cnt = which ? g_cnt_dn : g_cnt_up;
    int* ptr = which ? g_ptr_dn : g_ptr_up;
    int tid = threadIdx.x;
    int idx = blockIdx.x * SCAN_BS + tid;
    int c = (idx < NN) ? cnt[idx] : 0;
    s[tid] = c;
    __syncthreads();
    for (int off = 1; off < SCAN_BS; off <<= 1) {
        int v = (tid >= off) ? s[tid - off] : 0;
        __syncthreads();
        s[tid] += v;
        __syncthreads();
    }
    if (idx < NN) ptr[idx] = s[tid] - c;           // exclusive within block
    if (tid == SCAN_BS - 1) g_bsum[blockIdx.x] = s[tid];
}

__global__ void scan2_kernel() {
    __shared__ int s[256];
    int tid = threadIdx.x;
    int v = (tid < NBLK_SCAN) ? g_bsum[tid] : 0;
    s[tid] = v;
    __syncthreads();
    for (int off = 1; off < 256; off <<= 1) {
        int t = (tid >= off) ? s[tid - off] : 0;
        __syncthreads();
        s[tid] += t;
        __syncthreads();
    }
    if (tid < NBLK_SCAN) g_bsum[tid] = s[tid] - v; // exclusive
}

__global__ void scan3_kernel(int which) {
    int* ptr = which ? g_ptr_dn : g_ptr_up;
    int* cur = which ? g_cnt_dn : g_cnt_up;
    int i = blockIdx.x * blockDim.x + threadIdx.x;
    if (i < NN) {
        int p = ptr[i] + g_bsum[i / SCAN_BS];
        ptr[i] = p;
        cur[i] = p;                                 // cursor for fill
    }
    if (i == 0) ptr[NN] = NNZC;
}

__global__ void fill_kernel(const int* __restrict__ rows, const int* __restrict__ cols,
                            const float* __restrict__ vals, int which) {
    int e = blockIdx.x * blockDim.x + threadIdx.x;
    if (e >= NNZC) return;
    int r = rows[e];
    int* cur = which ? g_cnt_dn : g_cnt_up;
    int p = atomicAdd(&cur[r], 1);
    if (which) { g_col_dn[p] = cols[e]; g_cval_dn[p] = vals[e]; }
    else       { g_col_up[p] = cols[e]; g_cval_up[p] = vals[e]; }
}

// ---------------- dense GEMM + fused s2 = |h| @ a2 ----------------
// CONCAT=1: two heads of width 16 concatenated (FO=32), W layout [2][FI][16],
//           a2 layout [2][16] (contiguous 32 floats). Outputs S2a (head0), S2b (head1).
// CONCAT=0: single head, W [FI][FO], a2 [FO]. Output S2a only.
template <int FI, int FO, int CONCAT>
__global__ __launch_bounds__(256) void gemm_kernel(const float* __restrict__ Xext, int useGX,
                                                   const float* __restrict__ W,
                                                   const float* __restrict__ a2) {
    constexpr int NT = (FI >= 128) ? 32 : 64;   // nodes per block
    constexpr int G = 256 / FO;                 // node groups
    constexpr int TN = NT / G;                  // nodes per thread
    __shared__ float Ws[FI * FO];
    __shared__ float Xs[NT * FI];
    __shared__ float a2s[FO];
    __shared__ float sred[8 * TN];

    const float* X = useGX ? (const float*)g_X : Xext;
    int tid = threadIdx.x;
    for (int i = tid; i < FI * FO; i += 256) {
        float w;
        if (CONCAT) {
            int k = i / FO, j = i % FO;
            w = (j < 16) ? W[k * 16 + j] : W[FI * 16 + k * 16 + (j - 16)];
        } else {
            w = W[i];
        }
        Ws[i] = w;
    }
    if (tid < FO) a2s[tid] = a2[tid];
    int nb = blockIdx.x * NT;
    {
        const float4* src = (const float4*)(X + (size_t)nb * FI);
        float4* dst = (float4*)Xs;
        for (int i = tid; i < NT * FI / 4; i += 256) dst[i] = src[i];
    }
    __syncthreads();

    int j = tid % FO, grp = tid / FO, lane = tid & 31;
    float acc[TN];
#pragma unroll
    for (int t = 0; t < TN; ++t) acc[t] = 0.f;
    for (int k = 0; k < FI; ++k) {
        float w = Ws[k * FO + j];
#pragma unroll
        for (int t = 0; t < TN; ++t)
            acc[t] += Xs[(grp + G * t) * FI + k] * w;
    }
#pragma unroll
    for (int t = 0; t < TN; ++t) {
        int node = nb + grp + G * t;
        g_H[(size_t)node * FO + j] = acc[t];
    }
    float a = a2s[j];
    if (CONCAT) {
#pragma unroll
        for (int t = 0; t < TN; ++t) {
            float v = fabsf(acc[t]) * a;
            v += __shfl_xor_sync(0xffffffffu, v, 8);
            v += __shfl_xor_sync(0xffffffffu, v, 4);
            v += __shfl_xor_sync(0xffffffffu, v, 2);
            v += __shfl_xor_sync(0xffffffffu, v, 1);
            int node = nb + grp + G * t;
            if (lane == 0)  g_S2a[node] = v;   // head 0 (j 0..15)
            if (lane == 16) g_S2b[node] = v;   // head 1 (j 16..31)
        }
    } else {
        int wib = tid >> 5;
#pragma unroll
        for (int t = 0; t < TN; ++t) {
            float v = fabsf(acc[t]) * a;
            for (int off = 16; off; off >>= 1) v += __shfl_xor_sync(0xffffffffu, v, off);
            if (lane == 0) sred[wib * TN + t] = v;
        }
        __syncthreads();
        if (j == 0) {
#pragma unroll
            for (int t = 0; t < TN; ++t) {
                int node = nb + grp + G * t;
                g_S2a[node] = sred[(2 * grp) * TN + t] + sred[(2 * grp + 1) * TN + t];
            }
        }
    }
}

// ---------------- sparse attention aggregation (one warp per row) ----------------
// Row softmax: s1[row] is constant per segment and cancels -> weights use only s2[col].
__global__ __launch_bounds__(256) void agg16_kernel(int which, int useS2b, int hoff, int ooff) {
    int gw = (blockIdx.x * blockDim.x + threadIdx.x) >> 5;
    if (gw >= NN) return;
    const int* ptr = which ? g_ptr_dn : g_ptr_up;
    const int* __restrict__ col = which ? g_col_dn : g_col_up;
    const float* __restrict__ val = which ? g_cval_dn : g_cval_up;
    const float* __restrict__ s2 = useS2b ? g_S2b : g_S2a;
    int lane = threadIdx.x & 31;
    int start = ptr[gw], end = ptr[gw + 1];

    float m = -1e30f;
    for (int e = start + lane; e < end; e += 32) m = fmaxf(m, s2[col[e]]);
    for (int off = 16; off; off >>= 1) m = fmaxf(m, __shfl_xor_sync(0xffffffffu, m, off));

    float d = 0.f;
    for (int e = start + lane; e < end; e += 32) d += __expf(s2[col[e]] - m);
    for (int off = 16; off; off >>= 1) d += __shfl_xor_sync(0xffffffffu, d, off);
    float rd = (d > 0.f) ? 1.f / d : 0.f;

    int f = lane & 15, sub = lane >> 4;
    float acc = 0.f;
    for (int e = start + sub; e < end; e += 2) {
        int c = col[e];
        float w = __expf(s2[c] - m) * val[e];
        acc += w * g_H[c * 32 + hoff + f];
    }
    acc *= rd;
    acc += __shfl_xor_sync(0xffffffffu, acc, 16);
    if (lane < 16) g_X[gw * 32 + ooff + lane] = fmaxf(acc, 0.f);   // fused ReLU
}

__global__ __launch_bounds__(256) void agg64_kernel(int which, int addRelu) {
    int gw = (blockIdx.x * blockDim.x + threadIdx.x) >> 5;
    if (gw >= NN) return;
    const int* ptr = which ? g_ptr_dn : g_ptr_up;
    const int* __restrict__ col = which ? g_col_dn : g_col_up;
    const float* __restrict__ val = which ? g_cval_dn : g_cval_up;
    const float* __restrict__ s2 = g_S2a;
    int lane = threadIdx.x & 31;
    int start = ptr[gw], end = ptr[gw + 1];

    float m = -1e30f;
    for (int e = start + lane; e < end; e += 32) m = fmaxf(m, s2[col[e]]);
    for (int off = 16; off; off >>= 1) m = fmaxf(m, __shfl_xor_sync(0xffffffffu, m, off));

    float d = 0.f;
    for (int e = start + lane; e < end; e += 32) d += __expf(s2[col[e]] - m);
    for (int off = 16; off; off >>= 1) d += __shfl_xor_sync(0xffffffffu, d, off);
    float rd = (d > 0.f) ? 1.f / d : 0.f;

    const float2* __restrict__ H2 = (const float2*)g_H;
    float2 acc = make_float2(0.f, 0.f);
    for (int e = start; e < end; ++e) {
        int c = col[e];
        float w = __expf(s2[c] - m) * val[e];
        float2 hv = H2[c * 32 + lane];
        acc.x += w * hv.x;
        acc.y += w * hv.y;
    }
    acc.x *= rd; acc.y *= rd;
    float2* Y2 = (float2*)g_Y;
    int o = gw * 32 + lane;
    if (addRelu) {
        float2 p = Y2[o];
        acc.x = fmaxf(acc.x + p.x, 0.f);
        acc.y = fmaxf(acc.y + p.y, 0.f);
    }
    Y2[o] = acc;
}

// ---------------- pooling (batch ids sorted -> run-length accumulate) ----------------
__global__ void pool_accum_kernel(const int* __restrict__ batch) {
    int j = threadIdx.x;                       // feature 0..63
    int base = blockIdx.x * 128;
    int lim = min(base + 128, NN);
    int curg = batch[base];
    float run = 0.f, crun = 0.f;
    for (int i = base; i < lim; ++i) {
        int g = batch[i];
        if (g != curg) {
            atomicAdd(&g_psum[curg * 64 + j], run);
            if (j == 0) atomicAdd(&g_pcnt[curg], crun);
            run = 0.f; crun = 0.f; curg = g;
        }
        run += g_Y[(size_t)i * 64 + j];
        crun += 1.f;
    }
    atomicAdd(&g_psum[curg * 64 + j], run);
    if (j == 0) atomicAdd(&g_pcnt[curg], crun);
}

__global__ void pool_softmax_kernel(float* __restrict__ out) {
    int g = blockIdx.x, j = threadIdx.x;
    __shared__ float rm[2], rs[2];
    float c = g_pcnt[g];
    float mean = g_psum[g * 64 + j] / fmaxf(c, 1.0f);
    float m = mean;
    for (int off = 16; off; off >>= 1) m = fmaxf(m, __shfl_xor_sync(0xffffffffu, m, off));
    if ((j & 31) == 0) rm[j >> 5] = m;
    __syncthreads();
    m = fmaxf(rm[0], rm[1]);
    float e = expf(mean - m);
    float s = e;
    for (int off = 16; off; off >>= 1) s += __shfl_xor_sync(0xffffffffu, s, off);
    if ((j & 31) == 0) rs[j >> 5] = s;
    __syncthreads();
    s = rs[0] + rs[1];
    out[g * 64 + j] = e / s;
}

// ---------------- launch ----------------
extern "C" void kernel_launch(void* const* d_in, const int* in_sizes, int n_in,
                              void* d_out, int out_size) {
    const float* X1   = (const float*)d_in[0];
    const int*   idxu = (const int*)d_in[1];
    const float* valu = (const float*)d_in[2];
    const int*   idxd = (const int*)d_in[3];
    const float* vald = (const float*)d_in[4];
    const int*   batch = (const int*)d_in[5];
    const float* W1  = (const float*)d_in[6];
    const float* a21 = (const float*)d_in[8];
    const float* W2  = (const float*)d_in[9];
    const float* a22 = (const float*)d_in[11];
    const float* W4  = (const float*)d_in[12];
    const float* a24 = (const float*)d_in[14];
    float* out = (float*)d_out;

    const int EB = (NNZC + 255) / 256;           // 12500
    const int NB = (NN + 255) / 256;

    zero_kernel<<<NB, 256>>>();
    count_kernel<<<EB, 256>>>(idxu, 0);
    count_kernel<<<EB, 256>>>(idxd, 1);

    // CSR up
    scan1_kernel<<<NBLK_SCAN, SCAN_BS>>>(0);
    scan2_kernel<<<1, 256>>>();
    scan3_kernel<<<NB, 256>>>(0);
    fill_kernel<<<EB, 256>>>(idxu, idxu + NNZC, valu, 0);
    // CSR down
    scan1_kernel<<<NBLK_SCAN, SCAN_BS>>>(1);
    scan2_kernel<<<1, 256>>>();
    scan3_kernel<<<NB, 256>>>(1);
    fill_kernel<<<EB, 256>>>(idxd, idxd + NNZC, vald, 1);

    // layer 1: X1[N,128] -> h[N,32] (two heads), agg per head, ReLU -> g_X
    gemm_kernel<128, 32, 1><<<NN / 32, 256>>>(X1, 0, W1, a21);
    agg16_kernel<<<NN / 8, 256>>>(0, 0, 0, 0);    // head0: up
    agg16_kernel<<<NN / 8, 256>>>(1, 1, 16, 16);  // head1: down

    // layer 2: g_X[N,32] -> h[N,32], agg, ReLU -> g_X
    gemm_kernel<32, 32, 1><<<NN / 64, 256>>>(nullptr, 1, W2, a22);
    agg16_kernel<<<NN / 8, 256>>>(0, 0, 0, 0);
    agg16_kernel<<<NN / 8, 256>>>(1, 1, 16, 16);

    // layer 4: per-head [N,64], heads summed, ReLU -> g_Y
    gemm_kernel<32, 64, 0><<<NN / 64, 256>>>(nullptr, 1, W4, a24);
    agg64_kernel<<<NN / 8, 256>>>(0, 0);                        // head0: write
    gemm_kernel<32, 64, 0><<<NN / 64, 256>>>(nullptr, 1, W4 + 32 * 64, a24 + 64);
    agg64_kernel<<<NN / 8, 256>>>(1, 1);                        // head1: add + ReLU

    // pool + softmax
    pool_accum_kernel<<<(NN + 127) / 128, 64>>>(batch);
    pool_softmax_kernel<<<NG, 64>>>(out);
}

// round 5
// speedup vs baseline: 1.3171x; 1.3171x over previous
#include <cuda_runtime.h>

#define NN 200000
#define NNZC 3200000
#define NG 256
#define SCAN_BS 1024
#define NBLK_SCAN ((NN + SCAN_BS - 1) / SCAN_BS)   // 196

// ---------------- device scratch (no allocations allowed) ----------------
__device__ __align__(16) int   g_ptr_up[NN + 1];
__device__ __align__(16) int   g_ptr_dn[NN + 1];
__device__ __align__(16) int   g_cnt_up[NN];       // counts, then cursor
__device__ __align__(16) int   g_cnt_dn[NN];
__device__ __align__(16) int2  g_eu[NNZC];         // packed (col, val bits)
__device__ __align__(16) int2  g_ed[NNZC];
__device__ __align__(16) int   g_bsum[2][NBLK_SCAN];
__device__ __align__(16) float g_H[(size_t)NN * 64];
__device__ __align__(16) float g_X[(size_t)NN * 32];
__device__ __align__(16) float g_Y[(size_t)NN * 64];
__device__ __align__(16) float g_S2a[NN];          // holds exp(s2) per node
__device__ __align__(16) float g_S2b[NN];
__device__ __align__(16) float g_psum[NG * 64];
__device__ __align__(16) float g_pcnt[NG];

// ---------------- zero scratch that needs it ----------------
__global__ void zero_kernel() {
    int i = blockIdx.x * blockDim.x + threadIdx.x;
    if (i < NN) { g_cnt_up[i] = 0; g_cnt_dn[i] = 0; }
    if (i < NG * 64) g_psum[i] = 0.f;
    if (i < NG) g_pcnt[i] = 0.f;
}

// ---------------- CSR build (up + down fused) ----------------
__global__ void count_kernel(const int* __restrict__ ru, const int* __restrict__ rd) {
    int e = blockIdx.x * blockDim.x + threadIdx.x;
    if (e >= NNZC) return;
    atomicAdd(&g_cnt_up[ru[e]], 1);
    atomicAdd(&g_cnt_dn[rd[e]], 1);
}

__global__ __launch_bounds__(SCAN_BS) void scan1_kernel() {
    __shared__ int s[SCAN_BS];
    int which = blockIdx.y;
    const int* cnt = which ? g_cnt_dn : g_cnt_up;
    int* ptr = which ? g_ptr_dn : g_ptr_up;
    int tid = threadIdx.x;
    int idx = blockIdx.x * SCAN_BS + tid;
    int c = (idx < NN) ? cnt[idx] : 0;
    s[tid] = c;
    __syncthreads();
    for (int off = 1; off < SCAN_BS; off <<= 1) {
        int v = (tid >= off) ? s[tid - off] : 0;
        __syncthreads();
        s[tid] += v;
        __syncthreads();
    }
    if (idx < NN) ptr[idx] = s[tid] - c;           // exclusive within block
    if (tid == SCAN_BS - 1) g_bsum[which][blockIdx.x] = s[tid];
}

__global__ void scan2_kernel() {
    __shared__ int s[256];
    int which = blockIdx.x;
    int tid = threadIdx.x;
    int v = (tid < NBLK_SCAN) ? g_bsum[which][tid] : 0;
    s[tid] = v;
    __syncthreads();
    for (int off = 1; off < 256; off <<= 1) {
        int t = (tid >= off) ? s[tid - off] : 0;
        __syncthreads();
        s[tid] += t;
        __syncthreads();
    }
    if (tid < NBLK_SCAN) g_bsum[which][tid] = s[tid] - v; // exclusive
}

__global__ void scan3_kernel() {
    int which = blockIdx.y;
    int* ptr = which ? g_ptr_dn : g_ptr_up;
    int* cur = which ? g_cnt_dn : g_cnt_up;
    int i = blockIdx.x * blockDim.x + threadIdx.x;
    if (i < NN) {
        int p = ptr[i] + g_bsum[which][i / SCAN_BS];
        ptr[i] = p;
        cur[i] = p;                                 // cursor for fill
    }
    if (i == 0) ptr[NN] = NNZC;
}

__global__ void fill_kernel(const int* __restrict__ ru, const float* __restrict__ vu,
                            const int* __restrict__ rd, const float* __restrict__ vd) {
    int e = blockIdx.x * blockDim.x + threadIdx.x;
    if (e >= NNZC) return;
    {
        int p = atomicAdd(&g_cnt_up[ru[e]], 1);
        g_eu[p] = make_int2(ru[e + NNZC], __float_as_int(vu[e]));
    }
    {
        int p = atomicAdd(&g_cnt_dn[rd[e]], 1);
        g_ed[p] = make_int2(rd[e + NNZC], __float_as_int(vd[e]));
    }
}

// ---------------- dense GEMM + fused T = exp(|h| @ a2) ----------------
// CONCAT=1: two heads of width 16 concatenated (FO=32), W layout [2][FI][16],
//           a2 layout [2][16]. Outputs T into S2a (head0), S2b (head1).
// CONCAT=0: single head, W [FI][FO], a2 [FO]. Output S2a only.
template <int FI, int FO, int CONCAT>
__global__ __launch_bounds__(256) void gemm_kernel(const float* __restrict__ Xext, int useGX,
                                                   const float* __restrict__ W,
                                                   const float* __restrict__ a2) {
    constexpr int NT = (FI >= 128) ? 32 : 64;   // nodes per block
    constexpr int G = 256 / FO;                 // node groups
    constexpr int TN = NT / G;                  // nodes per thread
    __shared__ float Ws[FI * FO];
    __shared__ float Xs[NT * FI];
    __shared__ float a2s[FO];
    __shared__ float sred[8 * TN];

    const float* X = useGX ? (const float*)g_X : Xext;
    int tid = threadIdx.x;
    for (int i = tid; i < FI * FO; i += 256) {
        float w;
        if (CONCAT) {
            int k = i / FO, j = i % FO;
            w = (j < 16) ? W[k * 16 + j] : W[FI * 16 + k * 16 + (j - 16)];
        } else {
            w = W[i];
        }
        Ws[i] = w;
    }
    if (tid < FO) a2s[tid] = a2[tid];
    int nb = blockIdx.x * NT;
    {
        const float4* src = (const float4*)(X + (size_t)nb * FI);
        float4* dst = (float4*)Xs;
        for (int i = tid; i < NT * FI / 4; i += 256) dst[i] = src[i];
    }
    __syncthreads();

    int j = tid % FO, grp = tid / FO, lane = tid & 31;
    float acc[TN];
#pragma unroll
    for (int t = 0; t < TN; ++t) acc[t] = 0.f;
    for (int k = 0; k < FI; ++k) {
        float w = Ws[k * FO + j];
#pragma unroll
        for (int t = 0; t < TN; ++t)
            acc[t] += Xs[(grp + G * t) * FI + k] * w;
    }
#pragma unroll
    for (int t = 0; t < TN; ++t) {
        int node = nb + grp + G * t;
        g_H[(size_t)node * FO + j] = acc[t];
    }
    float a = a2s[j];
    if (CONCAT) {
#pragma unroll
        for (int t = 0; t < TN; ++t) {
            float v = fabsf(acc[t]) * a;
            v += __shfl_xor_sync(0xffffffffu, v, 8);
            v += __shfl_xor_sync(0xffffffffu, v, 4);
            v += __shfl_xor_sync(0xffffffffu, v, 2);
            v += __shfl_xor_sync(0xffffffffu, v, 1);
            int node = nb + grp + G * t;
            if (lane == 0)  g_S2a[node] = __expf(v);   // head 0 (j 0..15)
            if (lane == 16) g_S2b[node] = __expf(v);   // head 1 (j 16..31)
        }
    } else {
        int wib = tid >> 5;
#pragma unroll
        for (int t = 0; t < TN; ++t) {
            float v = fabsf(acc[t]) * a;
            for (int off = 16; off; off >>= 1) v += __shfl_xor_sync(0xffffffffu, v, off);
            if (lane == 0) sred[wib * TN + t] = v;
        }
        __syncthreads();
        if (j == 0) {
#pragma unroll
            for (int t = 0; t < TN; ++t) {
                int node = nb + grp + G * t;
                g_S2a[node] = __expf(sred[(2 * grp) * TN + t] + sred[(2 * grp + 1) * TN + t]);
            }
        }
    }
}

// ---------------- sparse attention aggregation: SINGLE fused pass ----------------
// att_ij = T[col_j]*val_j / sum_j T[col_j]  with T = exp(s2) precomputed per node.
// Accumulate unnormalized sum + denominator in one sweep, divide once at the end.
__global__ __launch_bounds__(256) void agg16_kernel(int which, int useS2b, int hoff, int ooff) {
    int gw = (blockIdx.x * blockDim.x + threadIdx.x) >> 5;
    if (gw >= NN) return;
    const int* ptr = which ? g_ptr_dn : g_ptr_up;
    const int2* __restrict__ E = which ? g_ed : g_eu;
    const float* __restrict__ T = useS2b ? g_S2b : g_S2a;
    int lane = threadIdx.x & 31;
    int start = ptr[gw], end = ptr[gw + 1];
    int f = lane & 15, sub = lane >> 4;

    float d = 0.f, acc = 0.f;
    for (int e = start + sub; e < end; e += 2) {
        int2 cv = E[e];
        float t = T[cv.x];
        d += t;
        acc += t * __int_as_float(cv.y) * g_H[cv.x * 32 + hoff + f];
    }
    acc += __shfl_xor_sync(0xffffffffu, acc, 16);
    d   += __shfl_xor_sync(0xffffffffu, d, 16);
    float r = (d > 0.f) ? acc / d : 0.f;
    if (lane < 16) g_X[gw * 32 + ooff + lane] = fmaxf(r, 0.f);   // fused ReLU
}

__global__ __launch_bounds__(256) void agg64_kernel(int which, int addRelu) {
    int gw = (blockIdx.x * blockDim.x + threadIdx.x) >> 5;
    if (gw >= NN) return;
    const int* ptr = which ? g_ptr_dn : g_ptr_up;
    const int2* __restrict__ E = which ? g_ed : g_eu;
    const float* __restrict__ T = g_S2a;
    int lane = threadIdx.x & 31;
    int start = ptr[gw], end = ptr[gw + 1];

    const float2* __restrict__ H2 = (const float2*)g_H;
    float d = 0.f;
    float2 acc = make_float2(0.f, 0.f);
    for (int e = start; e < end; ++e) {
        int2 cv = E[e];
        float t = T[cv.x];
        float w = t * __int_as_float(cv.y);
        d += t;
        float2 hv = H2[cv.x * 32 + lane];
        acc.x += w * hv.x;
        acc.y += w * hv.y;
    }
    float rd = (d > 0.f) ? 1.f / d : 0.f;
    acc.x *= rd; acc.y *= rd;
    float2* Y2 = (float2*)g_Y;
    int o = gw * 32 + lane;
    if (addRelu) {
        float2 p = Y2[o];
        acc.x = fmaxf(acc.x + p.x, 0.f);
        acc.y = fmaxf(acc.y + p.y, 0.f);
    }
    Y2[o] = acc;
}

// ---------------- pooling (batch ids sorted -> run-length accumulate) ----------------
__global__ void pool_accum_kernel(const int* __restrict__ batch) {
    int j = threadIdx.x;                       // feature 0..63
    int base = blockIdx.x * 128;
    int lim = min(base + 128, NN);
    int curg = batch[base];
    float run = 0.f, crun = 0.f;
    for (int i = base; i < lim; ++i) {
        int g = batch[i];
        if (g != curg) {
            atomicAdd(&g_psum[curg * 64 + j], run);
            if (j == 0) atomicAdd(&g_pcnt[curg], crun);
            run = 0.f; crun = 0.f; curg = g;
        }
        run += g_Y[(size_t)i * 64 + j];
        crun += 1.f;
    }
    atomicAdd(&g_psum[curg * 64 + j], run);
    if (j == 0) atomicAdd(&g_pcnt[curg], crun);
}

__global__ void pool_softmax_kernel(float* __restrict__ out) {
    int g = blockIdx.x, j = threadIdx.x;
    __shared__ float rm[2], rs[2];
    float c = g_pcnt[g];
    float mean = g_psum[g * 64 + j] / fmaxf(c, 1.0f);
    float m = mean;
    for (int off = 16; off; off >>= 1) m = fmaxf(m, __shfl_xor_sync(0xffffffffu, m, off));
    if ((j & 31) == 0) rm[j >> 5] = m;
    __syncthreads();
    m = fmaxf(rm[0], rm[1]);
    float e = expf(mean - m);
    float s = e;
    for (int off = 16; off; off >>= 1) s += __shfl_xor_sync(0xffffffffu, s, off);
    if ((j & 31) == 0) rs[j >> 5] = s;
    __syncthreads();
    s = rs[0] + rs[1];
    out[g * 64 + j] = e / s;
}

// ---------------- launch ----------------
extern "C" void kernel_launch(void* const* d_in, const int* in_sizes, int n_in,
                              void* d_out, int out_size) {
    const float* X1   = (const float*)d_in[0];
    const int*   idxu = (const int*)d_in[1];
    const float* valu = (const float*)d_in[2];
    const int*   idxd = (const int*)d_in[3];
    const float* vald = (const float*)d_in[4];
    const int*   batch = (const int*)d_in[5];
    const float* W1  = (const float*)d_in[6];
    const float* a21 = (const float*)d_in[8];
    const float* W2  = (const float*)d_in[9];
    const float* a22 = (const float*)d_in[11];
    const float* W4  = (const float*)d_in[12];
    const float* a24 = (const float*)d_in[14];
    float* out = (float*)d_out;

    const int EB = (NNZC + 255) / 256;           // 12500
    const int NB = (NN + 255) / 256;

    zero_kernel<<<NB, 256>>>();
    count_kernel<<<EB, 256>>>(idxu, idxd);
    scan1_kernel<<<dim3(NBLK_SCAN, 2), SCAN_BS>>>();
    scan2_kernel<<<2, 256>>>();
    scan3_kernel<<<dim3(NB, 2), 256>>>();
    fill_kernel<<<EB, 256>>>(idxu, valu, idxd, vald);

    // layer 1: X1[N,128] -> h[N,32] (two heads), agg per head, ReLU -> g_X
    gemm_kernel<128, 32, 1><<<NN / 32, 256>>>(X1, 0, W1, a21);
    agg16_kernel<<<NN / 8, 256>>>(0, 0, 0, 0);    // head0: up
    agg16_kernel<<<NN / 8, 256>>>(1, 1, 16, 16);  // head1: down

    // layer 2: g_X[N,32] -> h[N,32], agg, ReLU -> g_X
    gemm_kernel<32, 32, 1><<<NN / 64, 256>>>(nullptr, 1, W2, a22);
    agg16_kernel<<<NN / 8, 256>>>(0, 0, 0, 0);
    agg16_kernel<<<NN / 8, 256>>>(1, 1, 16, 16);

    // layer 4: per-head [N,64], heads summed, ReLU -> g_Y
    gemm_kernel<32, 64, 0><<<NN / 64, 256>>>(nullptr, 1, W4, a24);
    agg64_kernel<<<NN / 8, 256>>>(0, 0);                        // head0: write
    gemm_kernel<32, 64, 0><<<NN / 64, 256>>>(nullptr, 1, W4 + 32 * 64, a24 + 64);
    agg64_kernel<<<NN / 8, 256>>>(1, 1);                        // head1: add + ReLU

    // pool + softmax
    pool_accum_kernel<<<(NN + 127) / 128, 64>>>(batch);
    pool_softmax_kernel<<<NG, 64>>>(out);
}

// round 6
// speedup vs baseline: 1.4962x; 1.1360x over previous
#include <cuda_runtime.h>
#include <cuda_fp16.h>

#define NN 200000
#define NNZC 3200000
#define NG 256
#define SCAN_BS 1024
#define NBLK_SCAN ((NN + SCAN_BS - 1) / SCAN_BS)   // 196

// ---------------- device scratch (no allocations allowed) ----------------
__device__ __align__(16) int    g_ptr_up[NN + 1];
__device__ __align__(16) int    g_ptr_dn[NN + 1];
__device__ __align__(16) int    g_cnt_up[NN];       // counts, then cursor
__device__ __align__(16) int    g_cnt_dn[NN];
__device__ __align__(16) int2   g_eu[NNZC];         // packed (col, val bits)
__device__ __align__(16) int2   g_ed[NNZC];
__device__ __align__(16) int    g_bsum[2][NBLK_SCAN];
__device__ __align__(16) __half g_H16[(size_t)NN * 128];  // fp16 feature rows
__device__ __align__(16) float  g_X[(size_t)NN * 32];
__device__ __align__(16) float  g_Y[(size_t)NN * 64];
__device__ __align__(16) float  g_S2a[NN];          // exp(s2) head0 / up
__device__ __align__(16) float  g_S2b[NN];          // exp(s2) head1 / down
__device__ __align__(16) float  g_psum[NG * 64];
__device__ __align__(16) float  g_pcnt[NG];

// ---------------- zero scratch ----------------
__global__ void zero_kernel() {
    int i = blockIdx.x * blockDim.x + threadIdx.x;
    if (i < NN) { g_cnt_up[i] = 0; g_cnt_dn[i] = 0; }
    if (i < NG * 64) g_psum[i] = 0.f;
    if (i < NG) g_pcnt[i] = 0.f;
}

// ---------------- CSR build (up + down fused) ----------------
__global__ void count_kernel(const int* __restrict__ ru, const int* __restrict__ rd) {
    int e = blockIdx.x * blockDim.x + threadIdx.x;
    if (e >= NNZC) return;
    atomicAdd(&g_cnt_up[ru[e]], 1);
    atomicAdd(&g_cnt_dn[rd[e]], 1);
}

__global__ __launch_bounds__(SCAN_BS) void scan1_kernel() {
    __shared__ int s[SCAN_BS];
    int which = blockIdx.y;
    const int* cnt = which ? g_cnt_dn : g_cnt_up;
    int* ptr = which ? g_ptr_dn : g_ptr_up;
    int tid = threadIdx.x;
    int idx = blockIdx.x * SCAN_BS + tid;
    int c = (idx < NN) ? cnt[idx] : 0;
    s[tid] = c;
    __syncthreads();
    for (int off = 1; off < SCAN_BS; off <<= 1) {
        int v = (tid >= off) ? s[tid - off] : 0;
        __syncthreads();
        s[tid] += v;
        __syncthreads();
    }
    if (idx < NN) ptr[idx] = s[tid] - c;
    if (tid == SCAN_BS - 1) g_bsum[which][blockIdx.x] = s[tid];
}

__global__ void scan2_kernel() {
    __shared__ int s[256];
    int which = blockIdx.x;
    int tid = threadIdx.x;
    int v = (tid < NBLK_SCAN) ? g_bsum[which][tid] : 0;
    s[tid] = v;
    __syncthreads();
    for (int off = 1; off < 256; off <<= 1) {
        int t = (tid >= off) ? s[tid - off] : 0;
        __syncthreads();
        s[tid] += t;
        __syncthreads();
    }
    if (tid < NBLK_SCAN) g_bsum[which][tid] = s[tid] - v;
}

__global__ void scan3_kernel() {
    int which = blockIdx.y;
    int* ptr = which ? g_ptr_dn : g_ptr_up;
    int* cur = which ? g_cnt_dn : g_cnt_up;
    int i = blockIdx.x * blockDim.x + threadIdx.x;
    if (i < NN) {
        int p = ptr[i] + g_bsum[which][i / SCAN_BS];
        ptr[i] = p;
        cur[i] = p;
    }
    if (i == 0) ptr[NN] = NNZC;
}

__global__ void fill_kernel(const int* __restrict__ ru, const float* __restrict__ vu,
                            const int* __restrict__ rd, const float* __restrict__ vd) {
    int e = blockIdx.x * blockDim.x + threadIdx.x;
    if (e >= NNZC) return;
    int r0 = ru[e], c0 = ru[e + NNZC];
    int p0 = atomicAdd(&g_cnt_up[r0], 1);
    g_eu[p0] = make_int2(c0, __float_as_int(vu[e]));
    int r1 = rd[e], c1 = rd[e + NNZC];
    int p1 = atomicAdd(&g_cnt_dn[r1], 1);
    g_ed[p1] = make_int2(c1, __float_as_int(vd[e]));
}

// ---------------- layers 1/2 GEMM + fused T = exp(|h| @ a2) ----------------
// Two heads of width 16 concatenated (FO=32), W layout [2][FI][16], a2 [2][16].
// Writes fp16 H (row stride 32) and T into S2a (head0), S2b (head1).
template <int FI>
__global__ __launch_bounds__(256) void gemm12_kernel(const float* __restrict__ Xext, int useGX,
                                                     const float* __restrict__ W,
                                                     const float* __restrict__ a2) {
    constexpr int FO = 32;
    constexpr int NT = (FI >= 128) ? 32 : 64;   // nodes per block
    constexpr int G = 256 / FO;                 // 8 node groups
    constexpr int TN = NT / G;                  // nodes per thread
    __shared__ float Ws[FI * FO];
    __shared__ float Xs[NT * FI];
    __shared__ float a2s[FO];

    const float* X = useGX ? (const float*)g_X : Xext;
    int tid = threadIdx.x;
    for (int i = tid; i < FI * FO; i += 256) {
        int k = i / FO, j = i % FO;
        Ws[i] = (j < 16) ? W[k * 16 + j] : W[FI * 16 + k * 16 + (j - 16)];
    }
    if (tid < FO) a2s[tid] = a2[tid];
    int nb = blockIdx.x * NT;
    {
        const float4* src = (const float4*)(X + (size_t)nb * FI);
        float4* dst = (float4*)Xs;
        for (int i = tid; i < NT * FI / 4; i += 256) dst[i] = src[i];
    }
    __syncthreads();

    int j = tid % FO, grp = tid / FO, lane = tid & 31;
    float acc[TN];
#pragma unroll
    for (int t = 0; t < TN; ++t) acc[t] = 0.f;
    const float4* Xs4 = (const float4*)Xs;
#pragma unroll 4
    for (int k4 = 0; k4 < FI / 4; ++k4) {
        float w0 = Ws[(4 * k4 + 0) * FO + j];
        float w1 = Ws[(4 * k4 + 1) * FO + j];
        float w2 = Ws[(4 * k4 + 2) * FO + j];
        float w3 = Ws[(4 * k4 + 3) * FO + j];
#pragma unroll
        for (int t = 0; t < TN; ++t) {
            float4 x = Xs4[(grp + G * t) * (FI / 4) + k4];
            acc[t] += x.x * w0 + x.y * w1 + x.z * w2 + x.w * w3;
        }
    }
#pragma unroll
    for (int t = 0; t < TN; ++t) {
        int node = nb + grp + G * t;
        g_H16[(size_t)node * 32 + j] = __float2half_rn(acc[t]);
    }
    float a = a2s[j];
#pragma unroll
    for (int t = 0; t < TN; ++t) {
        float v = fabsf(acc[t]) * a;
        v += __shfl_xor_sync(0xffffffffu, v, 8);
        v += __shfl_xor_sync(0xffffffffu, v, 4);
        v += __shfl_xor_sync(0xffffffffu, v, 2);
        v += __shfl_xor_sync(0xffffffffu, v, 1);
        int node = nb + grp + G * t;
        if (lane == 0)  g_S2a[node] = __expf(v);   // head 0 (j 0..15)
        if (lane == 16) g_S2b[node] = __expf(v);   // head 1 (j 16..31)
    }
}

// ---------------- layer 4 GEMM (FI=32, FO=64, single head) ----------------
// Writes fp16 H (row stride 128, column offset hoff) and T into S2a/S2b.
__global__ __launch_bounds__(256) void gemm4_kernel(const float* __restrict__ W,
                                                    const float* __restrict__ a2,
                                                    int hoff, int headsel) {
    constexpr int FI = 32, FO = 64;
    constexpr int NT = 64;
    constexpr int G = 256 / FO;   // 4
    constexpr int TN = NT / G;    // 16
    __shared__ float Ws[FI * FO];
    __shared__ float Xs[NT * FI];
    __shared__ float a2s[FO];
    __shared__ float sred[8 * TN];

    int tid = threadIdx.x;
    for (int i = tid; i < FI * FO; i += 256) Ws[i] = W[i];
    if (tid < FO) a2s[tid] = a2[tid];
    int nb = blockIdx.x * NT;
    {
        const float4* src = (const float4*)(g_X + (size_t)nb * FI);
        float4* dst = (float4*)Xs;
        for (int i = tid; i < NT * FI / 4; i += 256) dst[i] = src[i];
    }
    __syncthreads();

    int j = tid % FO, grp = tid / FO, lane = tid & 31;
    float acc[TN];
#pragma unroll
    for (int t = 0; t < TN; ++t) acc[t] = 0.f;
    const float4* Xs4 = (const float4*)Xs;
#pragma unroll
    for (int k4 = 0; k4 < FI / 4; ++k4) {
        float w0 = Ws[(4 * k4 + 0) * FO + j];
        float w1 = Ws[(4 * k4 + 1) * FO + j];
        float w2 = Ws[(4 * k4 + 2) * FO + j];
        float w3 = Ws[(4 * k4 + 3) * FO + j];
#pragma unroll
        for (int t = 0; t < TN; ++t) {
            float4 x = Xs4[(grp + G * t) * (FI / 4) + k4];
            acc[t] += x.x * w0 + x.y * w1 + x.z * w2 + x.w * w3;
        }
    }
#pragma unroll
    for (int t = 0; t < TN; ++t) {
        int node = nb + grp + G * t;
        g_H16[(size_t)node * 128 + hoff + j] = __float2half_rn(acc[t]);
    }
    float a = a2s[j];
    int wib = tid >> 5;
#pragma unroll
    for (int t = 0; t < TN; ++t) {
        float v = fabsf(acc[t]) * a;
        for (int off = 16; off; off >>= 1) v += __shfl_xor_sync(0xffffffffu, v, off);
        if (lane == 0) sred[wib * TN + t] = v;
    }
    __syncthreads();
    if (j == 0) {
        float* Tout = headsel ? g_S2b : g_S2a;
#pragma unroll
        for (int t = 0; t < TN; ++t) {
            int node = nb + grp + G * t;
            Tout[node] = __expf(sred[(2 * grp) * TN + t] + sred[(2 * grp + 1) * TN + t]);
        }
    }
}

// ---------------- fused up+down aggregation, layers 1/2 (16 features/head) ----------------
// att_ij = T[col]*val / sum T[col]; single sweep, fp16 H gather, fused ReLU.
__global__ __launch_bounds__(256) void agg16c_kernel() {
    int gw = (blockIdx.x * blockDim.x + threadIdx.x) >> 5;
    if (gw >= NN) return;
    int lane = threadIdx.x & 31;
    int f = lane & 15, sub = lane >> 4;

    // head 0: up graph, H cols [0,16)
    float r0;
    {
        int start = g_ptr_up[gw], end = g_ptr_up[gw + 1];
        float d = 0.f, acc = 0.f;
        for (int e = start + sub; e < end; e += 2) {
            int2 cv = g_eu[e];
            float t = g_S2a[cv.x];
            d += t;
            acc += t * __int_as_float(cv.y) * __half2float(g_H16[(size_t)cv.x * 32 + f]);
        }
        acc += __shfl_xor_sync(0xffffffffu, acc, 16);
        d   += __shfl_xor_sync(0xffffffffu, d, 16);
        r0 = (d > 0.f) ? acc / d : 0.f;
    }
    // head 1: down graph, H cols [16,32)
    float r1;
    {
        int start = g_ptr_dn[gw], end = g_ptr_dn[gw + 1];
        float d = 0.f, acc = 0.f;
        for (int e = start + sub; e < end; e += 2) {
            int2 cv = g_ed[e];
            float t = g_S2b[cv.x];
            d += t;
            acc += t * __int_as_float(cv.y) * __half2float(g_H16[(size_t)cv.x * 32 + 16 + f]);
        }
        acc += __shfl_xor_sync(0xffffffffu, acc, 16);
        d   += __shfl_xor_sync(0xffffffffu, d, 16);
        r1 = (d > 0.f) ? acc / d : 0.f;
    }
    if (lane < 16) {
        g_X[gw * 32 + lane]      = fmaxf(r0, 0.f);
        g_X[gw * 32 + 16 + lane] = fmaxf(r1, 0.f);
    }
}

// ---------------- fused up+down aggregation, layer 4 (64 features, heads summed) ----------------
__global__ __launch_bounds__(256) void agg64c_kernel() {
    int gw = (blockIdx.x * blockDim.x + threadIdx.x) >> 5;
    if (gw >= NN) return;
    int lane = threadIdx.x & 31;
    const __half2* __restrict__ H2 = (const __half2*)g_H16;  // row = 64 half2

    float ax = 0.f, ay = 0.f;
    {   // head 0: up graph, cols [0,64)
        int start = g_ptr_up[gw], end = g_ptr_up[gw + 1];
        float d = 0.f, sx = 0.f, sy = 0.f;
        for (int e = start; e < end; ++e) {
            int2 cv = g_eu[e];
            float t = g_S2a[cv.x];
            float w = t * __int_as_float(cv.y);
            d += t;
            float2 hv = __half22float2(H2[(size_t)cv.x * 64 + lane]);
            sx += w * hv.x;
            sy += w * hv.y;
        }
        float rd = (d > 0.f) ? 1.f / d : 0.f;
        ax += sx * rd; ay += sy * rd;
    }
    {   // head 1: down graph, cols [64,128)
        int start = g_ptr_dn[gw], end = g_ptr_dn[gw + 1];
        float d = 0.f, sx = 0.f, sy = 0.f;
        for (int e = start; e < end; ++e) {
            int2 cv = g_ed[e];
            float t = g_S2b[cv.x];
            float w = t * __int_as_float(cv.y);
            d += t;
            float2 hv = __half22float2(H2[(size_t)cv.x * 64 + 32 + lane]);
            sx += w * hv.x;
            sy += w * hv.y;
        }
        float rd = (d > 0.f) ? 1.f / d : 0.f;
        ax += sx * rd; ay += sy * rd;
    }
    float2* Y2 = (float2*)g_Y;
    Y2[gw * 32 + lane] = make_float2(fmaxf(ax, 0.f), fmaxf(ay, 0.f));
}

// ---------------- pooling (batch ids sorted -> run-length accumulate) ----------------
__global__ void pool_accum_kernel(const int* __restrict__ batch) {
    int j = threadIdx.x;                       // feature 0..63
    int base = blockIdx.x * 128;
    int lim = min(base + 128, NN);
    int curg = batch[base];
    float run = 0.f, crun = 0.f;
    for (int i = base; i < lim; ++i) {
        int g = batch[i];
        if (g != curg) {
            atomicAdd(&g_psum[curg * 64 + j], run);
            if (j == 0) atomicAdd(&g_pcnt[curg], crun);
            run = 0.f; crun = 0.f; curg = g;
        }
        run += g_Y[(size_t)i * 64 + j];
        crun += 1.f;
    }
    atomicAdd(&g_psum[curg * 64 + j], run);
    if (j == 0) atomicAdd(&g_pcnt[curg], crun);
}

__global__ void pool_softmax_kernel(float* __restrict__ out) {
    int g = blockIdx.x, j = threadIdx.x;
    __shared__ float rm[2], rs[2];
    float c = g_pcnt[g];
    float mean = g_psum[g * 64 + j] / fmaxf(c, 1.0f);
    float m = mean;
    for (int off = 16; off; off >>= 1) m = fmaxf(m, __shfl_xor_sync(0xffffffffu, m, off));
    if ((j & 31) == 0) rm[j >> 5] = m;
    __syncthreads();
    m = fmaxf(rm[0], rm[1]);
    float e = expf(mean - m);
    float s = e;
    for (int off = 16; off; off >>= 1) s += __shfl_xor_sync(0xffffffffu, s, off);
    if ((j & 31) == 0) rs[j >> 5] = s;
    __syncthreads();
    s = rs[0] + rs[1];
    out[g * 64 + j] = e / s;
}

// ---------------- launch ----------------
extern "C" void kernel_launch(void* const* d_in, const int* in_sizes, int n_in,
                              void* d_out, int out_size) {
    const float* X1   = (const float*)d_in[0];
    const int*   idxu = (const int*)d_in[1];
    const float* valu = (const float*)d_in[2];
    const int*   idxd = (const int*)d_in[3];
    const float* vald = (const float*)d_in[4];
    const int*   batch = (const int*)d_in[5];
    const float* W1  = (const float*)d_in[6];
    const float* a21 = (const float*)d_in[8];
    const float* W2  = (const float*)d_in[9];
    const float* a22 = (const float*)d_in[11];
    const float* W4  = (const float*)d_in[12];
    const float* a24 = (const float*)d_in[14];
    float* out = (float*)d_out;

    const int EB = (NNZC + 255) / 256;
    const int NB = (NN + 255) / 256;

    zero_kernel<<<NB, 256>>>();
    count_kernel<<<EB, 256>>>(idxu, idxd);
    scan1_kernel<<<dim3(NBLK_SCAN, 2), SCAN_BS>>>();
    scan2_kernel<<<2, 256>>>();
    scan3_kernel<<<dim3(NB, 2), 256>>>();
    fill_kernel<<<EB, 256>>>(idxu, valu, idxd, vald);

    // layer 1
    gemm12_kernel<128><<<NN / 32, 256>>>(X1, 0, W1, a21);
    agg16c_kernel<<<NN / 8, 256>>>();
    // layer 2
    gemm12_kernel<32><<<NN / 64, 256>>>(nullptr, 1, W2, a22);
    agg16c_kernel<<<NN / 8, 256>>>();
    // layer 4
    gemm4_kernel<<<NN / 64, 256>>>(W4, a24, 0, 0);
    gemm4_kernel<<<NN / 64, 256>>>(W4 + 32 * 64, a24 + 64, 64, 1);
    agg64c_kernel<<<NN / 8, 256>>>();

    // pool + softmax
    pool_accum_kernel<<<(NN + 127) / 128, 64>>>(batch);
    pool_softmax_kernel<<<NG, 64>>>(out);
}

// round 7
// speedup vs baseline: 1.7159x; 1.1469x over previous
#include <cuda_runtime.h>
#include <cuda_fp16.h>

#define NN 200000
#define NNZC 3200000
#define NG 256
#define SCAN_BS 1024
#define NBLK_SCAN ((NN + SCAN_BS - 1) / SCAN_BS)   // 196

// ---------------- device scratch (no allocations allowed) ----------------
__device__ __align__(16) int    g_ptr_up[NN + 1];
__device__ __align__(16) int    g_ptr_dn[NN + 1];
__device__ __align__(16) int    g_cnt_up[NN];       // counts, then cursor
__device__ __align__(16) int    g_cnt_dn[NN];
__device__ __align__(16) int2   g_eu[NNZC];         // packed (col, val bits)
__device__ __align__(16) int2   g_ed[NNZC];
__device__ __align__(16) int    g_bsum[2][NBLK_SCAN];
__device__ __align__(16) __half g_H16[(size_t)NN * 32];   // per-layer GEMM output (fp16)
__device__ __align__(16) __half g_X16[(size_t)NN * 32];   // layer-2 agg output (fp16)
__device__ __align__(16) __half g_U16[(size_t)NN * 64];   // layer-4 aggregated up|dn (fp16)
__device__ __align__(16) float  g_X[(size_t)NN * 32];     // layer-1 agg output (fp32)
__device__ __align__(16) float  g_S2a[NN];          // exp(s2) head0 / up
__device__ __align__(16) float  g_S2b[NN];          // exp(s2) head1 / down
__device__ __align__(16) float  g_psum[NG * 64];
__device__ __align__(16) float  g_pcnt[NG];

// ---------------- zero scratch ----------------
__global__ void zero_kernel() {
    int i = blockIdx.x * blockDim.x + threadIdx.x;
    if (i < NN) { g_cnt_up[i] = 0; g_cnt_dn[i] = 0; }
    if (i < NG * 64) g_psum[i] = 0.f;
    if (i < NG) g_pcnt[i] = 0.f;
}

// ---------------- CSR build (up + down fused) ----------------
__global__ void count_kernel(const int* __restrict__ ru, const int* __restrict__ rd) {
    int e = blockIdx.x * blockDim.x + threadIdx.x;
    if (e >= NNZC) return;
    atomicAdd(&g_cnt_up[ru[e]], 1);
    atomicAdd(&g_cnt_dn[rd[e]], 1);
}

__global__ __launch_bounds__(SCAN_BS) void scan1_kernel() {
    __shared__ int s[SCAN_BS];
    int which = blockIdx.y;
    const int* cnt = which ? g_cnt_dn : g_cnt_up;
    int* ptr = which ? g_ptr_dn : g_ptr_up;
    int tid = threadIdx.x;
    int idx = blockIdx.x * SCAN_BS + tid;
    int c = (idx < NN) ? cnt[idx] : 0;
    s[tid] = c;
    __syncthreads();
    for (int off = 1; off < SCAN_BS; off <<= 1) {
        int v = (tid >= off) ? s[tid - off] : 0;
        __syncthreads();
        s[tid] += v;
        __syncthreads();
    }
    if (idx < NN) ptr[idx] = s[tid] - c;
    if (tid == SCAN_BS - 1) g_bsum[which][blockIdx.x] = s[tid];
}

__global__ void scan2_kernel() {
    __shared__ int s[256];
    int which = blockIdx.x;
    int tid = threadIdx.x;
    int v = (tid < NBLK_SCAN) ? g_bsum[which][tid] : 0;
    s[tid] = v;
    __syncthreads();
    for (int off = 1; off < 256; off <<= 1) {
        int t = (tid >= off) ? s[tid - off] : 0;
        __syncthreads();
        s[tid] += t;
        __syncthreads();
    }
    if (tid < NBLK_SCAN) g_bsum[which][tid] = s[tid] - v;
}

__global__ void scan3_kernel() {
    int which = blockIdx.y;
    int* ptr = which ? g_ptr_dn : g_ptr_up;
    int* cur = which ? g_cnt_dn : g_cnt_up;
    int i = blockIdx.x * blockDim.x + threadIdx.x;
    if (i < NN) {
        int p = ptr[i] + g_bsum[which][i / SCAN_BS];
        ptr[i] = p;
        cur[i] = p;
    }
    if (i == 0) ptr[NN] = NNZC;
}

__global__ void fill_kernel(const int* __restrict__ ru, const float* __restrict__ vu,
                            const int* __restrict__ rd, const float* __restrict__ vd) {
    int e = blockIdx.x * blockDim.x + threadIdx.x;
    if (e >= NNZC) return;
    int r0 = ru[e], c0 = ru[e + NNZC];
    int p0 = atomicAdd(&g_cnt_up[r0], 1);
    g_eu[p0] = make_int2(c0, __float_as_int(vu[e]));
    int r1 = rd[e], c1 = rd[e + NNZC];
    int p1 = atomicAdd(&g_cnt_dn[r1], 1);
    g_ed[p1] = make_int2(c1, __float_as_int(vd[e]));
}

// ---------------- layers 1/2 GEMM + fused T = exp(|h| @ a2) ----------------
// Two heads of width 16 concatenated (FO=32), W layout [2][FI][16], a2 [2][16].
// Writes fp16 H (row stride 32 halves) and T into S2a (head0), S2b (head1).
template <int FI>
__global__ __launch_bounds__(256) void gemm12_kernel(const float* __restrict__ Xext, int useGX,
                                                     const float* __restrict__ W,
                                                     const float* __restrict__ a2) {
    constexpr int FO = 32;
    constexpr int NT = (FI >= 128) ? 32 : 64;
    constexpr int G = 256 / FO;                 // 8
    constexpr int TN = NT / G;
    __shared__ float Ws[FI * FO];
    __shared__ float Xs[NT * FI];
    __shared__ float a2s[FO];

    const float* X = useGX ? (const float*)g_X : Xext;
    int tid = threadIdx.x;
    for (int i = tid; i < FI * FO; i += 256) {
        int k = i / FO, j = i % FO;
        Ws[i] = (j < 16) ? W[k * 16 + j] : W[FI * 16 + k * 16 + (j - 16)];
    }
    if (tid < FO) a2s[tid] = a2[tid];
    int nb = blockIdx.x * NT;
    {
        const float4* src = (const float4*)(X + (size_t)nb * FI);
        float4* dst = (float4*)Xs;
        for (int i = tid; i < NT * FI / 4; i += 256) dst[i] = src[i];
    }
    __syncthreads();

    int j = tid % FO, grp = tid / FO, lane = tid & 31;
    float acc[TN];
#pragma unroll
    for (int t = 0; t < TN; ++t) acc[t] = 0.f;
    const float4* Xs4 = (const float4*)Xs;
#pragma unroll 4
    for (int k4 = 0; k4 < FI / 4; ++k4) {
        float w0 = Ws[(4 * k4 + 0) * FO + j];
        float w1 = Ws[(4 * k4 + 1) * FO + j];
        float w2 = Ws[(4 * k4 + 2) * FO + j];
        float w3 = Ws[(4 * k4 + 3) * FO + j];
#pragma unroll
        for (int t = 0; t < TN; ++t) {
            float4 x = Xs4[(grp + G * t) * (FI / 4) + k4];
            acc[t] += x.x * w0 + x.y * w1 + x.z * w2 + x.w * w3;
        }
    }
#pragma unroll
    for (int t = 0; t < TN; ++t) {
        int node = nb + grp + G * t;
        g_H16[(size_t)node * 32 + j] = __float2half_rn(acc[t]);
    }
    float a = a2s[j];
#pragma unroll
    for (int t = 0; t < TN; ++t) {
        float v = fabsf(acc[t]) * a;
        v += __shfl_xor_sync(0xffffffffu, v, 8);
        v += __shfl_xor_sync(0xffffffffu, v, 4);
        v += __shfl_xor_sync(0xffffffffu, v, 2);
        v += __shfl_xor_sync(0xffffffffu, v, 1);
        int node = nb + grp + G * t;
        if (lane == 0)  g_S2a[node] = __expf(v);   // head 0 (j 0..15)
        if (lane == 16) g_S2b[node] = __expf(v);   // head 1 (j 16..31)
    }
}

// ---------------- fused up+down agg, layers 1/2 (16 features/head, half2 loads) ----------------
// 4 sub-groups of 8 lanes, each handles one edge per iteration; half2 feature loads.
// out16: 0 -> write g_X (float2), 1 -> write g_X16 (half2)
__global__ __launch_bounds__(256) void agg16c_kernel(int out16) {
    int gw = (blockIdx.x * blockDim.x + threadIdx.x) >> 5;
    int lane = threadIdx.x & 31;
    int sub = lane >> 3, f2 = lane & 7;
    const __half2* __restrict__ H2 = (const __half2*)g_H16;  // row = 16 half2

    float2 r0, r1;
    {   // head 0: up graph, half2 cols [0,8)
        int start = g_ptr_up[gw], end = g_ptr_up[gw + 1];
        float d = 0.f;
        float2 acc = make_float2(0.f, 0.f);
        for (int e = start + sub; e < end; e += 4) {
            int2 cv = g_eu[e];
            float t = g_S2a[cv.x];
            float w = t * __int_as_float(cv.y);
            d += t;
            float2 hv = __half22float2(H2[(size_t)cv.x * 16 + f2]);
            acc.x += w * hv.x;
            acc.y += w * hv.y;
        }
        acc.x += __shfl_xor_sync(0xffffffffu, acc.x, 8);
        acc.y += __shfl_xor_sync(0xffffffffu, acc.y, 8);
        d     += __shfl_xor_sync(0xffffffffu, d, 8);
        acc.x += __shfl_xor_sync(0xffffffffu, acc.x, 16);
        acc.y += __shfl_xor_sync(0xffffffffu, acc.y, 16);
        d     += __shfl_xor_sync(0xffffffffu, d, 16);
        float rd = (d > 0.f) ? 1.f / d : 0.f;
        r0 = make_float2(fmaxf(acc.x * rd, 0.f), fmaxf(acc.y * rd, 0.f));
    }
    {   // head 1: down graph, half2 cols [8,16)
        int start = g_ptr_dn[gw], end = g_ptr_dn[gw + 1];
        float d = 0.f;
        float2 acc = make_float2(0.f, 0.f);
        for (int e = start + sub; e < end; e += 4) {
            int2 cv = g_ed[e];
            float t = g_S2b[cv.x];
            float w = t * __int_as_float(cv.y);
            d += t;
            float2 hv = __half22float2(H2[(size_t)cv.x * 16 + 8 + f2]);
            acc.x += w * hv.x;
            acc.y += w * hv.y;
        }
        acc.x += __shfl_xor_sync(0xffffffffu, acc.x, 8);
        acc.y += __shfl_xor_sync(0xffffffffu, acc.y, 8);
        d     += __shfl_xor_sync(0xffffffffu, d, 8);
        acc.x += __shfl_xor_sync(0xffffffffu, acc.x, 16);
        acc.y += __shfl_xor_sync(0xffffffffu, acc.y, 16);
        d     += __shfl_xor_sync(0xffffffffu, d, 16);
        float rd = (d > 0.f) ? 1.f / d : 0.f;
        r1 = make_float2(fmaxf(acc.x * rd, 0.f), fmaxf(acc.y * rd, 0.f));
    }
    if (lane < 8) {
        if (out16) {
            __half2* X2 = (__half2*)g_X16;
            X2[gw * 16 + f2]     = __float22half2_rn(r0);
            X2[gw * 16 + 8 + f2] = __float22half2_rn(r1);
        } else {
            float2* X2 = (float2*)g_X;
            X2[gw * 16 + f2]     = r0;
            X2[gw * 16 + 8 + f2] = r1;
        }
    }
}

// ---------------- layer-4 T kernel: T = exp(|X16 @ W4h| @ a2h), no H store ----------------
__global__ __launch_bounds__(256) void t4_kernel(const float* __restrict__ W,
                                                 const float* __restrict__ a2, int headsel) {
    constexpr int FI = 32, FO = 64;
    constexpr int NT = 64;
    constexpr int G = 256 / FO;   // 4
    constexpr int TN = NT / G;    // 16
    __shared__ float Ws[FI * FO];
    __shared__ float Xs[NT * FI];
    __shared__ float a2s[FO];
    __shared__ float sred[8 * TN];

    int tid = threadIdx.x;
    for (int i = tid; i < FI * FO; i += 256) Ws[i] = W[i];
    if (tid < FO) a2s[tid] = a2[tid];
    int nb = blockIdx.x * NT;
    {
        const __half2* src = (const __half2*)g_X16 + (size_t)nb * 16;
        float2* dst = (float2*)Xs;
        for (int i = tid; i < NT * 16; i += 256) dst[i] = __half22float2(src[i]);
    }
    __syncthreads();

    int j = tid % FO, grp = tid / FO, lane = tid & 31;
    float acc[TN];
#pragma unroll
    for (int t = 0; t < TN; ++t) acc[t] = 0.f;
    const float4* Xs4 = (const float4*)Xs;
#pragma unroll
    for (int k4 = 0; k4 < FI / 4; ++k4) {
        float w0 = Ws[(4 * k4 + 0) * FO + j];
        float w1 = Ws[(4 * k4 + 1) * FO + j];
        float w2 = Ws[(4 * k4 + 2) * FO + j];
        float w3 = Ws[(4 * k4 + 3) * FO + j];
#pragma unroll
        for (int t = 0; t < TN; ++t) {
            float4 x = Xs4[(grp + G * t) * (FI / 4) + k4];
            acc[t] += x.x * w0 + x.y * w1 + x.z * w2 + x.w * w3;
        }
    }
    float a = a2s[j];
    int wib = tid >> 5;
#pragma unroll
    for (int t = 0; t < TN; ++t) {
        float v = fabsf(acc[t]) * a;
        for (int off = 16; off; off >>= 1) v += __shfl_xor_sync(0xffffffffu, v, off);
        if (lane == 0) sred[wib * TN + t] = v;
    }
    __syncthreads();
    if (j == 0) {
        float* Tout = headsel ? g_S2b : g_S2a;
#pragma unroll
        for (int t = 0; t < TN; ++t) {
            int node = nb + grp + G * t;
            Tout[node] = __expf(sred[(2 * grp) * TN + t] + sred[(2 * grp + 1) * TN + t]);
        }
    }
}

// ---------------- layer-4 aggregation of X16 (32 features, up|dn -> U16[64]) ----------------
__global__ __launch_bounds__(256) void agg4_kernel() {
    int gw = (blockIdx.x * blockDim.x + threadIdx.x) >> 5;
    int lane = threadIdx.x & 31;
    int sub = lane >> 4, f2 = lane & 15;
    const __half2* __restrict__ X2 = (const __half2*)g_X16;  // row = 16 half2

    float2 up, dn;
    {   // up graph
        int start = g_ptr_up[gw], end = g_ptr_up[gw + 1];
        float d = 0.f;
        float2 acc = make_float2(0.f, 0.f);
        for (int e = start + sub; e < end; e += 2) {
            int2 cv = g_eu[e];
            float t = g_S2a[cv.x];
            float w = t * __int_as_float(cv.y);
            d += t;
            float2 hv = __half22float2(X2[(size_t)cv.x * 16 + f2]);
            acc.x += w * hv.x;
            acc.y += w * hv.y;
        }
        acc.x += __shfl_xor_sync(0xffffffffu, acc.x, 16);
        acc.y += __shfl_xor_sync(0xffffffffu, acc.y, 16);
        d     += __shfl_xor_sync(0xffffffffu, d, 16);
        float rd = (d > 0.f) ? 1.f / d : 0.f;
        up = make_float2(acc.x * rd, acc.y * rd);
    }
    {   // down graph
        int start = g_ptr_dn[gw], end = g_ptr_dn[gw + 1];
        float d = 0.f;
        float2 acc = make_float2(0.f, 0.f);
        for (int e = start + sub; e < end; e += 2) {
            int2 cv = g_ed[e];
            float t = g_S2b[cv.x];
            float w = t * __int_as_float(cv.y);
            d += t;
            float2 hv = __half22float2(X2[(size_t)cv.x * 16 + f2]);
            acc.x += w * hv.x;
            acc.y += w * hv.y;
        }
        acc.x += __shfl_xor_sync(0xffffffffu, acc.x, 16);
        acc.y += __shfl_xor_sync(0xffffffffu, acc.y, 16);
        d     += __shfl_xor_sync(0xffffffffu, d, 16);
        float rd = (d > 0.f) ? 1.f / d : 0.f;
        dn = make_float2(acc.x * rd, acc.y * rd);
    }
    if (lane < 16) {
        __half2* U2 = (__half2*)g_U16;     // row = 32 half2: [0,16) up, [16,32) dn
        U2[gw * 32 + f2]      = __float22half2_rn(up);
        U2[gw * 32 + 16 + f2] = __float22half2_rn(dn);
    }
}

// ---------------- final GEMM: out = relu(U16 @ W4flat[64][64]) fused with mean-pool ----------------
__global__ __launch_bounds__(256) void gemmfinal_kernel(const float* __restrict__ W4,
                                                        const int* __restrict__ batch) {
    constexpr int FI = 64, FO = 64;
    constexpr int NT = 64;
    constexpr int G = 4, TN = 16;
    __shared__ float Ws[FI * FO];          // W4 flat [2][32][64] == combined [64][64]
    __shared__ float Xs[NT * FI];
    __shared__ float sred2[4][64];

    int tid = threadIdx.x;
    for (int i = tid; i < FI * FO; i += 256) Ws[i] = W4[i];
    int nb = blockIdx.x * NT;
    {
        const __half2* src = (const __half2*)g_U16 + (size_t)nb * 32;
        float2* dst = (float2*)Xs;
        for (int i = tid; i < NT * 32; i += 256) dst[i] = __half22float2(src[i]);
    }
    __syncthreads();

    int j = tid % FO, grp = tid / FO;
    float acc[TN];
#pragma unroll
    for (int t = 0; t < TN; ++t) acc[t] = 0.f;
    const float4* Xs4 = (const float4*)Xs;
#pragma unroll 4
    for (int k4 = 0; k4 < FI / 4; ++k4) {
        float w0 = Ws[(4 * k4 + 0) * FO + j];
        float w1 = Ws[(4 * k4 + 1) * FO + j];
        float w2 = Ws[(4 * k4 + 2) * FO + j];
        float w3 = Ws[(4 * k4 + 3) * FO + j];
#pragma unroll
        for (int t = 0; t < TN; ++t) {
            float4 x = Xs4[(grp + G * t) * (FI / 4) + k4];
            acc[t] += x.x * w0 + x.y * w1 + x.z * w2 + x.w * w3;
        }
    }

    // pooled accumulation (batch sorted -> uniform iff first == last)
    int b0 = batch[nb];
    int bL = batch[nb + NT - 1];
    if (b0 == bL) {
        float s = 0.f;
#pragma unroll
        for (int t = 0; t < TN; ++t) s += fmaxf(acc[t], 0.f);
        sred2[grp][j] = s;
        __syncthreads();
        if (tid < 64) {
            float tot = sred2[0][tid] + sred2[1][tid] + sred2[2][tid] + sred2[3][tid];
            atomicAdd(&g_psum[b0 * 64 + tid], tot);
        }
        if (tid == 0) atomicAdd(&g_pcnt[b0], (float)NT);
    } else {
#pragma unroll
        for (int t = 0; t < TN; ++t) {
            int node = nb + grp + G * t;
            int b = batch[node];
            atomicAdd(&g_psum[b * 64 + j], fmaxf(acc[t], 0.f));
            if (j == 0) atomicAdd(&g_pcnt[b], 1.f);
        }
    }
}

__global__ void pool_softmax_kernel(float* __restrict__ out) {
    int g = blockIdx.x, j = threadIdx.x;
    __shared__ float rm[2], rs[2];
    float c = g_pcnt[g];
    float mean = g_psum[g * 64 + j] / fmaxf(c, 1.0f);
    float m = mean;
    for (int off = 16; off; off >>= 1) m = fmaxf(m, __shfl_xor_sync(0xffffffffu, m, off));
    if ((j & 31) == 0) rm[j >> 5] = m;
    __syncthreads();
    m = fmaxf(rm[0], rm[1]);
    float e = expf(mean - m);
    float s = e;
    for (int off = 16; off; off >>= 1) s += __shfl_xor_sync(0xffffffffu, s, off);
    if ((j & 31) == 0) rs[j >> 5] = s;
    __syncthreads();
    s = rs[0] + rs[1];
    out[g * 64 + j] = e / s;
}

// ---------------- launch ----------------
extern "C" void kernel_launch(void* const* d_in, const int* in_sizes, int n_in,
                              void* d_out, int out_size) {
    const float* X1   = (const float*)d_in[0];
    const int*   idxu = (const int*)d_in[1];
    const float* valu = (const float*)d_in[2];
    const int*   idxd = (const int*)d_in[3];
    const float* vald = (const float*)d_in[4];
    const int*   batch = (const int*)d_in[5];
    const float* W1  = (const float*)d_in[6];
    const float* a21 = (const float*)d_in[8];
    const float* W2  = (const float*)d_in[9];
    const float* a22 = (const float*)d_in[11];
    const float* W4  = (const float*)d_in[12];
    const float* a24 = (const float*)d_in[14];
    float* out = (float*)d_out;

    const int EB = (NNZC + 255) / 256;
    const int NB = (NN + 255) / 256;

    zero_kernel<<<NB, 256>>>();
    count_kernel<<<EB, 256>>>(idxu, idxd);
    scan1_kernel<<<dim3(NBLK_SCAN, 2), SCAN_BS>>>();
    scan2_kernel<<<2, 256>>>();
    scan3_kernel<<<dim3(NB, 2), 256>>>();
    fill_kernel<<<EB, 256>>>(idxu, valu, idxd, vald);

    // layer 1
    gemm12_kernel<128><<<NN / 32, 256>>>(X1, 0, W1, a21);
    agg16c_kernel<<<NN / 8, 256>>>(0);          // -> g_X (fp32)
    // layer 2
    gemm12_kernel<32><<<NN / 64, 256>>>(nullptr, 1, W2, a22);
    agg16c_kernel<<<NN / 8, 256>>>(1);          // -> g_X16 (fp16)
    // layer 4: T per head, aggregate X16, then GEMM+ReLU+pool
    t4_kernel<<<NN / 64, 256>>>(W4, a24, 0);
    t4_kernel<<<NN / 64, 256>>>(W4 + 32 * 64, a24 + 64, 1);
    agg4_kernel<<<NN / 8, 256>>>();
    gemmfinal_kernel<<<NN / 64, 256>>>(W4, batch);

    pool_softmax_kernel<<<NG, 64>>>(out);
}